// round 7
// baseline (speedup 1.0000x reference)
#include <cuda_runtime.h>

#define D_MODEL 1024
#define NHEAD   16
#define DK      64
#define SEQ     2048
#define BATCH   4
#define MTOT    (BATCH*SEQ)   // 8192

// ---------------- scratch (device globals; allocation-free) ----------------
__device__ float g_Q[(size_t)MTOT * D_MODEL];
__device__ float g_K[(size_t)MTOT * D_MODEL];
__device__ float g_V[(size_t)MTOT * D_MODEL];
__device__ float g_X[(size_t)MTOT * D_MODEL];

// ---------------- packed f32x2 helpers (Blackwell FFMA2 path) ----------------
static __device__ __forceinline__ unsigned long long pk2(float x, float y) {
    unsigned long long r;
    asm("mov.b64 %0, {%1, %2};" : "=l"(r) : "f"(x), "f"(y));
    return r;
}
static __device__ __forceinline__ void upk2(unsigned long long v, float &x, float &y) {
    asm("mov.b64 {%0, %1}, %2;" : "=f"(x), "=f"(y) : "l"(v));
}
static __device__ __forceinline__ unsigned long long ffma2(unsigned long long a,
                                                           unsigned long long b,
                                                           unsigned long long c) {
    unsigned long long d;
    asm("fma.rn.f32x2 %0, %1, %2, %3;" : "=l"(d) : "l"(a), "l"(b), "l"(c));
    return d;
}
static __device__ __forceinline__ unsigned long long fmul2(unsigned long long a,
                                                           unsigned long long b) {
    unsigned long long d;
    asm("mul.rn.f32x2 %0, %1, %2;" : "=l"(d) : "l"(a), "l"(b));
    return d;
}

// ---------------- GEMM: C[M,N] = alpha * (X[M,K] @ W[N,K]^T + bias[N]) ----------------
// MODE 0: out[m*N + n]                     (plain row-major)
// MODE 1: out[((b*H + h)*S + s)*DK + d]    (head-split layout for attention)
template <int MODE>
__global__ __launch_bounds__(256)
void gemm_wt_bias(const float* __restrict__ X, const float* __restrict__ W,
                  const float* __restrict__ bias, float* __restrict__ out,
                  float alpha)
{
    constexpr int BM = 128, BN = 128, BK = 16;
    __shared__ float As[BM][BK];        // [row][k]  (a read via 2-addr broadcast)
    __shared__ float Bs[BK][BN + 2];    // [k][n]    (+2 pad: conflict-free scatter store)

    const int tid = threadIdx.x;
    const int tx = tid & 15, ty = tid >> 4;
    const int row0 = blockIdx.y * BM;
    const int col0 = blockIdx.x * BN;
    const int K = D_MODEL;

    unsigned long long acc[8][4];
#pragma unroll
    for (int i = 0; i < 8; i++)
#pragma unroll
        for (int j = 0; j < 4; j++) acc[i][j] = 0ULL;  // bit pattern {0.f, 0.f}

    for (int kt = 0; kt < K; kt += BK) {
#pragma unroll
        for (int it = 0; it < 2; it++) {
            int f = tid + it * 256;
            int r = f >> 2, k4 = (f & 3) * 4;
            float4 av = *(const float4*)&X[(size_t)(row0 + r) * K + kt + k4];
            *(float4*)&As[r][k4] = av;
            float4 bv = *(const float4*)&W[(size_t)(col0 + r) * K + kt + k4];
            Bs[k4 + 0][r] = bv.x; Bs[k4 + 1][r] = bv.y;
            Bs[k4 + 2][r] = bv.z; Bs[k4 + 3][r] = bv.w;
        }
        __syncthreads();
#pragma unroll
        for (int k = 0; k < BK; k++) {
            unsigned long long a2[8], b2[4];
#pragma unroll
            for (int i = 0; i < 8; i++) { float a = As[ty * 8 + i][k]; a2[i] = pk2(a, a); }
#pragma unroll
            for (int j = 0; j < 4; j++)
                b2[j] = *(const unsigned long long*)&Bs[k][tx * 8 + 2 * j];
#pragma unroll
            for (int i = 0; i < 8; i++)
#pragma unroll
                for (int j = 0; j < 4; j++)
                    acc[i][j] = ffma2(a2[i], b2[j], acc[i][j]);
        }
        __syncthreads();
    }

    // epilogue
    float bcol[8];
#pragma unroll
    for (int j = 0; j < 8; j++) bcol[j] = bias[col0 + tx * 8 + j];
#pragma unroll
    for (int i = 0; i < 8; i++) {
        int m = row0 + ty * 8 + i;
        float c[8];
#pragma unroll
        for (int j = 0; j < 4; j++) { upk2(acc[i][j], c[2 * j], c[2 * j + 1]); }
#pragma unroll
        for (int j = 0; j < 8; j++) c[j] = (c[j] + bcol[j]) * alpha;
        if (MODE == 0) {
            float* o = &out[(size_t)m * D_MODEL + col0 + tx * 8];
#pragma unroll
            for (int j = 0; j < 8; j++) o[j] = c[j];
        } else {
            int b = m >> 11, s = m & (SEQ - 1);
            int n0 = col0 + tx * 8;
            int h = n0 >> 6, d0 = n0 & 63;
            float* o = &out[(((size_t)(b * NHEAD + h)) * SEQ + s) * DK + d0];
#pragma unroll
            for (int j = 0; j < 8; j++) o[j] = c[j];
        }
    }
}

// ---------------- Flash attention (fp32, streaming softmax) ----------------
// One block: one (b,h) pair x 128 query rows. Iterates kv in tiles of 64.
// Score scale 1/8 is pre-folded into Q projection.
#define BQ   128
#define BKV  64
#define APAD 68   // row pad (floats): keeps 16B alignment, de-clusters banks

__global__ __launch_bounds__(256)
void flash_attn(const float* __restrict__ Qp, const float* __restrict__ Kp,
                const float* __restrict__ Vp, float* __restrict__ Xo)
{
    extern __shared__ float sm[];
    float (*Qs)[APAD] = (float(*)[APAD])sm;                          // 128 x 68
    float (*Ks)[APAD] = (float(*)[APAD])(sm + BQ * APAD);            // 64 x 68
    float (*Vs)[APAD] = (float(*)[APAD])(sm + (BQ + BKV) * APAD);    // 64 x 68
    float (*Ps)[APAD] = (float(*)[APAD])(sm + (BQ + 2 * BKV) * APAD);// 128 x 68

    const int tid = threadIdx.x;
    const int tx = tid & 15, ty = tid >> 4;
    const int bh = blockIdx.y;
    const int q0 = blockIdx.x * BQ;

    const float* Qb = Qp + (size_t)bh * SEQ * DK;
    const float* Kb = Kp + (size_t)bh * SEQ * DK;
    const float* Vb = Vp + (size_t)bh * SEQ * DK;

    // Q tile: 128 x 64 floats = 2048 float4
#pragma unroll
    for (int it = 0; it < 8; it++) {
        int f = tid + it * 256;
        int r = f >> 4, c4 = (f & 15) * 4;
        *(float4*)&Qs[r][c4] = *(const float4*)&Qb[(size_t)(q0 + r) * DK + c4];
    }

    float mrow[8], lrow[8];
    unsigned long long o2[8][2];
#pragma unroll
    for (int i = 0; i < 8; i++) {
        mrow[i] = -3.0e38f; lrow[i] = 0.f;
        o2[i][0] = 0ULL; o2[i][1] = 0ULL;
    }

    for (int kv0 = 0; kv0 < SEQ; kv0 += BKV) {
        __syncthreads();   // prior tile's phase-3 must finish before overwrite
#pragma unroll
        for (int it = 0; it < 4; it++) {
            int f = tid + it * 256;
            int r = f >> 4, c4 = (f & 15) * 4;
            *(float4*)&Ks[r][c4] = *(const float4*)&Kb[(size_t)(kv0 + r) * DK + c4];
            *(float4*)&Vs[r][c4] = *(const float4*)&Vb[(size_t)(kv0 + r) * DK + c4];
        }
        __syncthreads();

        // phase 1: S = Q K^T  (micro-tile 8q x 4k per thread, packed over d)
        unsigned long long sa[8][4];
#pragma unroll
        for (int i = 0; i < 8; i++)
#pragma unroll
            for (int j = 0; j < 4; j++) sa[i][j] = 0ULL;

#pragma unroll 8
        for (int d2 = 0; d2 < 32; d2++) {
            unsigned long long q2[8], k2[4];
#pragma unroll
            for (int i = 0; i < 8; i++)
                q2[i] = *(const unsigned long long*)&Qs[ty * 8 + i][2 * d2];
#pragma unroll
            for (int j = 0; j < 4; j++)
                k2[j] = *(const unsigned long long*)&Ks[tx * 4 + j][2 * d2];
#pragma unroll
            for (int i = 0; i < 8; i++)
#pragma unroll
                for (int j = 0; j < 4; j++)
                    sa[i][j] = ffma2(q2[i], k2[j], sa[i][j]);
        }

        float s[8][4];
#pragma unroll
        for (int i = 0; i < 8; i++)
#pragma unroll
            for (int j = 0; j < 4; j++) {
                float x0, x1; upk2(sa[i][j], x0, x1);
                s[i][j] = x0 + x1;          // scale already folded into Q
            }

        // phase 2: online softmax (row groups = 16 tx lanes, aligned in warp)
#pragma unroll
        for (int i = 0; i < 8; i++) {
            float mt = s[i][0];
#pragma unroll
            for (int j = 1; j < 4; j++) mt = fmaxf(mt, s[i][j]);
#pragma unroll
            for (int off = 1; off < 16; off <<= 1)
                mt = fmaxf(mt, __shfl_xor_sync(0xffffffffu, mt, off));
            float mnew = fmaxf(mrow[i], mt);
            float scale = __expf(mrow[i] - mnew);
            float p[4], rs = 0.f;
#pragma unroll
            for (int j = 0; j < 4; j++) { p[j] = __expf(s[i][j] - mnew); rs += p[j]; }
#pragma unroll
            for (int off = 1; off < 16; off <<= 1)
                rs += __shfl_xor_sync(0xffffffffu, rs, off);
            lrow[i] = lrow[i] * scale + rs;
            mrow[i] = mnew;
            unsigned long long sc2 = pk2(scale, scale);
            o2[i][0] = fmul2(o2[i][0], sc2);
            o2[i][1] = fmul2(o2[i][1], sc2);
            Ps[ty * 8 + i][tx * 4 + 0] = p[0];
            Ps[ty * 8 + i][tx * 4 + 1] = p[1];
            Ps[ty * 8 + i][tx * 4 + 2] = p[2];
            Ps[ty * 8 + i][tx * 4 + 3] = p[3];
        }
        __syncthreads();

        // phase 3: O += P V  (thread owns 8 rows x 4 d-cols, packed over d)
#pragma unroll 4
        for (int k = 0; k < BKV; k++) {
            unsigned long long v0 = *(const unsigned long long*)&Vs[k][tx * 4];
            unsigned long long v1 = *(const unsigned long long*)&Vs[k][tx * 4 + 2];
#pragma unroll
            for (int i = 0; i < 8; i++) {
                float pv = Ps[ty * 8 + i][k];
                unsigned long long p2 = pk2(pv, pv);
                o2[i][0] = ffma2(p2, v0, o2[i][0]);
                o2[i][1] = ffma2(p2, v1, o2[i][1]);
            }
        }
    }

    // epilogue: O /= l, write back in (B,S,D) layout (un-split heads)
    const int b = bh >> 4, h = bh & 15;
#pragma unroll
    for (int i = 0; i < 8; i++) {
        float inv = 1.0f / lrow[i];
        float x0, x1, x2, x3;
        upk2(o2[i][0], x0, x1); upk2(o2[i][1], x2, x3);
        float4 v = make_float4(x0 * inv, x1 * inv, x2 * inv, x3 * inv);
        size_t srow = (size_t)(q0 + ty * 8 + i);
        *(float4*)&Xo[((size_t)b * SEQ + srow) * D_MODEL + h * DK + tx * 4] = v;
    }
}

// ---------------- launch ----------------
extern "C" void kernel_launch(void* const* d_in, const int* in_sizes, int n_in,
                              void* d_out, int out_size)
{
    const float* q  = (const float*)d_in[0];
    const float* k  = (const float*)d_in[1];
    const float* v  = (const float*)d_in[2];
    const float* Wq = (const float*)d_in[3];
    const float* bq = (const float*)d_in[4];
    const float* Wk = (const float*)d_in[5];
    const float* bk = (const float*)d_in[6];
    const float* Wv = (const float*)d_in[7];
    const float* bv = (const float*)d_in[8];
    const float* Wo = (const float*)d_in[9];
    const float* bo = (const float*)d_in[10];
    float* out = (float*)d_out;

    float *gQ, *gK, *gV, *gX;
    cudaGetSymbolAddress((void**)&gQ, g_Q);
    cudaGetSymbolAddress((void**)&gK, g_K);
    cudaGetSymbolAddress((void**)&gV, g_V);
    cudaGetSymbolAddress((void**)&gX, g_X);

    dim3 gg(D_MODEL / 128, MTOT / 128);   // (8, 64)

    // projections; 1/sqrt(dk)=0.125 folded into Q
    gemm_wt_bias<1><<<gg, 256>>>(q, Wq, bq, gQ, 0.125f);
    gemm_wt_bias<1><<<gg, 256>>>(k, Wk, bk, gK, 1.0f);
    gemm_wt_bias<1><<<gg, 256>>>(v, Wv, bv, gV, 1.0f);

    // flash attention
    int smem = (BQ + 2 * BKV + BQ) * APAD * (int)sizeof(float);  // 104448 B
    cudaFuncSetAttribute(flash_attn, cudaFuncAttributeMaxDynamicSharedMemorySize, smem);
    flash_attn<<<dim3(SEQ / BQ, BATCH * NHEAD), 256, smem>>>(gQ, gK, gV, gX);

    // output projection
    gemm_wt_bias<0><<<gg, 256>>>(gX, Wo, bo, out, 1.0f);
}

// round 9
// speedup vs baseline: 1.2237x; 1.2237x over previous
#include <cuda_runtime.h>

#define D_MODEL 1024
#define NHEAD   16
#define DK      64
#define SEQ     2048
#define BATCH   4
#define MTOT    (BATCH*SEQ)   // 8192

// ---------------- scratch (device globals; allocation-free) ----------------
__device__ float g_Q[(size_t)MTOT * D_MODEL];
__device__ float g_K[(size_t)MTOT * D_MODEL];
__device__ float g_V[(size_t)MTOT * D_MODEL];
__device__ float g_X[(size_t)MTOT * D_MODEL];

// ---------------- packed f32x2 helpers (Blackwell FFMA2 path) ----------------
static __device__ __forceinline__ unsigned long long pk2(float x, float y) {
    unsigned long long r;
    asm("mov.b64 %0, {%1, %2};" : "=l"(r) : "f"(x), "f"(y));
    return r;
}
static __device__ __forceinline__ void upk2(unsigned long long v, float &x, float &y) {
    asm("mov.b64 {%0, %1}, %2;" : "=f"(x), "=f"(y) : "l"(v));
}
static __device__ __forceinline__ unsigned long long ffma2(unsigned long long a,
                                                           unsigned long long b,
                                                           unsigned long long c) {
    unsigned long long d;
    asm("fma.rn.f32x2 %0, %1, %2, %3;" : "=l"(d) : "l"(a), "l"(b), "l"(c));
    return d;
}
static __device__ __forceinline__ unsigned long long fmul2(unsigned long long a,
                                                           unsigned long long b) {
    unsigned long long d;
    asm("mul.rn.f32x2 %0, %1, %2;" : "=l"(d) : "l"(a), "l"(b));
    return d;
}

// ---------------- GEMM: C[M,N] = alpha * (X[M,K] @ W[N,K]^T + bias[N]) ----------------
// Thread owns 8 rows (ty*8+i) x 8 cols: pairs at {tx*2+32*j, +1}, j=0..3.
// Bs reads are stride-2 across lanes -> conflict-free.
// MODE 0: out[m*N + n]; MODE 1: head-split out[((b*H+h)*S + s)*DK + d]
template <int MODE>
__global__ __launch_bounds__(256)
void gemm_wt_bias(const float* __restrict__ X, const float* __restrict__ W,
                  const float* __restrict__ bias, float* __restrict__ out,
                  float alpha)
{
    constexpr int BM = 128, BN = 128, BK = 16;
    __shared__ float As[BM][BK];
    __shared__ float Bs[BK][BN + 2];

    const int tid = threadIdx.x;
    const int tx = tid & 15, ty = tid >> 4;
    const int row0 = blockIdx.y * BM;
    const int col0 = blockIdx.x * BN;
    const int K = D_MODEL;

    unsigned long long acc[8][4];
#pragma unroll
    for (int i = 0; i < 8; i++)
#pragma unroll
        for (int j = 0; j < 4; j++) acc[i][j] = 0ULL;

    for (int kt = 0; kt < K; kt += BK) {
#pragma unroll
        for (int it = 0; it < 2; it++) {
            int f = tid + it * 256;
            int r = f >> 2, k4 = (f & 3) * 4;
            float4 av = *(const float4*)&X[(size_t)(row0 + r) * K + kt + k4];
            *(float4*)&As[r][k4] = av;
            float4 bv = *(const float4*)&W[(size_t)(col0 + r) * K + kt + k4];
            Bs[k4 + 0][r] = bv.x; Bs[k4 + 1][r] = bv.y;
            Bs[k4 + 2][r] = bv.z; Bs[k4 + 3][r] = bv.w;
        }
        __syncthreads();
#pragma unroll
        for (int k = 0; k < BK; k++) {
            unsigned long long a2[8], b2[4];
#pragma unroll
            for (int i = 0; i < 8; i++) { float a = As[ty * 8 + i][k]; a2[i] = pk2(a, a); }
#pragma unroll
            for (int j = 0; j < 4; j++)
                b2[j] = *(const unsigned long long*)&Bs[k][tx * 2 + 32 * j];
#pragma unroll
            for (int i = 0; i < 8; i++)
#pragma unroll
                for (int j = 0; j < 4; j++)
                    acc[i][j] = ffma2(a2[i], b2[j], acc[i][j]);
        }
        __syncthreads();
    }

    // epilogue: columns col0 + tx*2 + 32*j (+1)
    float bcol[8];
#pragma unroll
    for (int j = 0; j < 4; j++) {
        bcol[2 * j]     = bias[col0 + tx * 2 + 32 * j];
        bcol[2 * j + 1] = bias[col0 + tx * 2 + 32 * j + 1];
    }
#pragma unroll
    for (int i = 0; i < 8; i++) {
        int m = row0 + ty * 8 + i;
#pragma unroll
        for (int j = 0; j < 4; j++) {
            float c0, c1; upk2(acc[i][j], c0, c1);
            c0 = (c0 + bcol[2 * j]) * alpha;
            c1 = (c1 + bcol[2 * j + 1]) * alpha;
            int n0 = col0 + tx * 2 + 32 * j;
            if (MODE == 0) {
                *(float2*)&out[(size_t)m * D_MODEL + n0] = make_float2(c0, c1);
            } else {
                int b = m >> 11, s = m & (SEQ - 1);
                int h = n0 >> 6, d0 = n0 & 63;
                *(float2*)&out[(((size_t)(b * NHEAD + h)) * SEQ + s) * DK + d0] =
                    make_float2(c0, c1);
            }
        }
    }
}

// ---------------- Flash attention (fp32, streaming softmax) ----------------
// APAD=66 (stride ≡ 2 mod 32): phase-1 K loads (k = tx+16j) conflict-free,
// phase-3 V loads (d = tx*2 / tx*2+32) conflict-free. Tile loads use float2.
#define BQ   128
#define BKV  64
#define APAD 66

__global__ __launch_bounds__(256)
void flash_attn(const float* __restrict__ Qp, const float* __restrict__ Kp,
                const float* __restrict__ Vp, float* __restrict__ Xo)
{
    extern __shared__ float sm[];
    float (*Qs)[APAD] = (float(*)[APAD])sm;                          // 128 x 66
    float (*Ks)[APAD] = (float(*)[APAD])(sm + BQ * APAD);            // 64 x 66
    float (*Vs)[APAD] = (float(*)[APAD])(sm + (BQ + BKV) * APAD);    // 64 x 66
    float (*Ps)[APAD] = (float(*)[APAD])(sm + (BQ + 2 * BKV) * APAD);// 128 x 66

    const int tid = threadIdx.x;
    const int tx = tid & 15, ty = tid >> 4;
    const int bh = blockIdx.y;
    const int q0 = blockIdx.x * BQ;

    const float* Qb = Qp + (size_t)bh * SEQ * DK;
    const float* Kb = Kp + (size_t)bh * SEQ * DK;
    const float* Vb = Vp + (size_t)bh * SEQ * DK;

    // Q tile: 128 rows x 64 floats = 4096 float2, 256 threads -> 16 iters
#pragma unroll
    for (int it = 0; it < 16; it++) {
        int f = tid + it * 256;
        int r = f >> 5, c2 = (f & 31) * 2;
        *(float2*)&Qs[r][c2] = *(const float2*)&Qb[(size_t)(q0 + r) * DK + c2];
    }

    float mrow[8], lrow[8];
    unsigned long long o2[8][2];
#pragma unroll
    for (int i = 0; i < 8; i++) {
        mrow[i] = -3.0e38f; lrow[i] = 0.f;
        o2[i][0] = 0ULL; o2[i][1] = 0ULL;
    }

    for (int kv0 = 0; kv0 < SEQ; kv0 += BKV) {
        __syncthreads();   // prior tile's phase-3 must finish before overwrite
#pragma unroll
        for (int it = 0; it < 8; it++) {
            int f = tid + it * 256;
            int r = f >> 5, c2 = (f & 31) * 2;
            *(float2*)&Ks[r][c2] = *(const float2*)&Kb[(size_t)(kv0 + r) * DK + c2];
            *(float2*)&Vs[r][c2] = *(const float2*)&Vb[(size_t)(kv0 + r) * DK + c2];
        }
        __syncthreads();

        // phase 1: S = Q K^T  (thread: 8 q-rows x 4 k-cols at k = tx+16j)
        unsigned long long sa[8][4];
#pragma unroll
        for (int i = 0; i < 8; i++)
#pragma unroll
            for (int j = 0; j < 4; j++) sa[i][j] = 0ULL;

#pragma unroll 8
        for (int d2 = 0; d2 < 32; d2++) {
            unsigned long long q2[8], k2[4];
#pragma unroll
            for (int i = 0; i < 8; i++)
                q2[i] = *(const unsigned long long*)&Qs[ty * 8 + i][2 * d2];
#pragma unroll
            for (int j = 0; j < 4; j++)
                k2[j] = *(const unsigned long long*)&Ks[tx + 16 * j][2 * d2];
#pragma unroll
            for (int i = 0; i < 8; i++)
#pragma unroll
                for (int j = 0; j < 4; j++)
                    sa[i][j] = ffma2(q2[i], k2[j], sa[i][j]);
        }

        float s[8][4];
#pragma unroll
        for (int i = 0; i < 8; i++)
#pragma unroll
            for (int j = 0; j < 4; j++) {
                float x0, x1; upk2(sa[i][j], x0, x1);
                s[i][j] = x0 + x1;          // scale already folded into Q
            }

        // phase 2: online softmax (16 tx lanes of a row group hold all 64 k)
#pragma unroll
        for (int i = 0; i < 8; i++) {
            float mt = s[i][0];
#pragma unroll
            for (int j = 1; j < 4; j++) mt = fmaxf(mt, s[i][j]);
#pragma unroll
            for (int off = 1; off < 16; off <<= 1)
                mt = fmaxf(mt, __shfl_xor_sync(0xffffffffu, mt, off));
            float mnew = fmaxf(mrow[i], mt);
            float scale = __expf(mrow[i] - mnew);
            float p[4], rs = 0.f;
#pragma unroll
            for (int j = 0; j < 4; j++) { p[j] = __expf(s[i][j] - mnew); rs += p[j]; }
#pragma unroll
            for (int off = 1; off < 16; off <<= 1)
                rs += __shfl_xor_sync(0xffffffffu, rs, off);
            lrow[i] = lrow[i] * scale + rs;
            mrow[i] = mnew;
            unsigned long long sc2 = pk2(scale, scale);
            o2[i][0] = fmul2(o2[i][0], sc2);
            o2[i][1] = fmul2(o2[i][1], sc2);
            Ps[ty * 8 + i][tx + 16 * 0] = p[0];
            Ps[ty * 8 + i][tx + 16 * 1] = p[1];
            Ps[ty * 8 + i][tx + 16 * 2] = p[2];
            Ps[ty * 8 + i][tx + 16 * 3] = p[3];
        }
        __syncthreads();

        // phase 3: O += P V  (thread d-cols: {tx*2, tx*2+1} and {tx*2+32, +33})
#pragma unroll 4
        for (int k = 0; k < BKV; k++) {
            unsigned long long v0 = *(const unsigned long long*)&Vs[k][tx * 2];
            unsigned long long v1 = *(const unsigned long long*)&Vs[k][tx * 2 + 32];
#pragma unroll
            for (int i = 0; i < 8; i++) {
                float pv = Ps[ty * 8 + i][k];
                unsigned long long p2 = pk2(pv, pv);
                o2[i][0] = ffma2(p2, v0, o2[i][0]);
                o2[i][1] = ffma2(p2, v1, o2[i][1]);
            }
        }
    }

    // epilogue: O /= l, write back in (B,S,D) layout (un-split heads)
    const int b = bh >> 4, h = bh & 15;
#pragma unroll
    for (int i = 0; i < 8; i++) {
        float inv = 1.0f / lrow[i];
        float x0, x1, x2, x3;
        upk2(o2[i][0], x0, x1); upk2(o2[i][1], x2, x3);
        size_t srow = (size_t)(q0 + ty * 8 + i);
        size_t base = ((size_t)b * SEQ + srow) * D_MODEL + h * DK;
        *(float2*)&Xo[base + tx * 2]      = make_float2(x0 * inv, x1 * inv);
        *(float2*)&Xo[base + tx * 2 + 32] = make_float2(x2 * inv, x3 * inv);
    }
}

// ---------------- launch ----------------
extern "C" void kernel_launch(void* const* d_in, const int* in_sizes, int n_in,
                              void* d_out, int out_size)
{
    const float* q  = (const float*)d_in[0];
    const float* k  = (const float*)d_in[1];
    const float* v  = (const float*)d_in[2];
    const float* Wq = (const float*)d_in[3];
    const float* bq = (const float*)d_in[4];
    const float* Wk = (const float*)d_in[5];
    const float* bk = (const float*)d_in[6];
    const float* Wv = (const float*)d_in[7];
    const float* bv = (const float*)d_in[8];
    const float* Wo = (const float*)d_in[9];
    const float* bo = (const float*)d_in[10];
    float* out = (float*)d_out;

    float *gQ, *gK, *gV, *gX;
    cudaGetSymbolAddress((void**)&gQ, g_Q);
    cudaGetSymbolAddress((void**)&gK, g_K);
    cudaGetSymbolAddress((void**)&gV, g_V);
    cudaGetSymbolAddress((void**)&gX, g_X);

    dim3 gg(D_MODEL / 128, MTOT / 128);   // (8, 64)

    // projections; 1/sqrt(dk)=0.125 folded into Q
    gemm_wt_bias<1><<<gg, 256>>>(q, Wq, bq, gQ, 0.125f);
    gemm_wt_bias<1><<<gg, 256>>>(k, Wk, bk, gK, 1.0f);
    gemm_wt_bias<1><<<gg, 256>>>(v, Wv, bv, gV, 1.0f);

    // flash attention
    int smem = (BQ + 2 * BKV + BQ) * APAD * (int)sizeof(float);  // 101376 B
    cudaFuncSetAttribute(flash_attn, cudaFuncAttributeMaxDynamicSharedMemorySize, smem);
    flash_attn<<<dim3(SEQ / BQ, BATCH * NHEAD), 256, smem>>>(gQ, gK, gV, gX);

    // output projection
    gemm_wt_bias<0><<<gg, 256>>>(gX, Wo, bo, out, 1.0f);
}

// round 16
// speedup vs baseline: 1.2321x; 1.0069x over previous
#include <cuda_runtime.h>

#define D_MODEL 1024
#define NHEAD   16
#define DK      64
#define SEQ     2048
#define BATCH   4
#define MTOT    (BATCH*SEQ)   // 8192

// ---------------- scratch (device globals; allocation-free) ----------------
__device__ float g_Q[(size_t)MTOT * D_MODEL];
__device__ float g_K[(size_t)MTOT * D_MODEL];
__device__ float g_V[(size_t)MTOT * D_MODEL];
__device__ float g_X[(size_t)MTOT * D_MODEL];

// ---------------- packed f32x2 helpers (Blackwell FFMA2 path) ----------------
static __device__ __forceinline__ unsigned long long pk2(float x, float y) {
    unsigned long long r;
    asm("mov.b64 %0, {%1, %2};" : "=l"(r) : "f"(x), "f"(y));
    return r;
}
static __device__ __forceinline__ void upk2(unsigned long long v, float &x, float &y) {
    asm("mov.b64 {%0, %1}, %2;" : "=f"(x), "=f"(y) : "l"(v));
}
static __device__ __forceinline__ unsigned long long ffma2(unsigned long long a,
                                                           unsigned long long b,
                                                           unsigned long long c) {
    unsigned long long d;
    asm("fma.rn.f32x2 %0, %1, %2, %3;" : "=l"(d) : "l"(a), "l"(b), "l"(c));
    return d;
}
static __device__ __forceinline__ unsigned long long fmul2(unsigned long long a,
                                                           unsigned long long b) {
    unsigned long long d;
    asm("mul.rn.f32x2 %0, %1, %2;" : "=l"(d) : "l"(a), "l"(b));
    return d;
}

// ---------------- GEMM: C[M,N] = alpha * (X[M,K] @ W[N,K]^T + bias[N]) ----------------
// Thread owns 8 rows (ty*8+i) x 8 cols: pairs at {tx*2+32*j, +1}, j=0..3.
// Bs reads are stride-2 across lanes -> conflict-free.
// MODE 0: out[m*N + n]; MODE 1: head-split out[((b*H+h)*S + s)*DK + d]
template <int MODE>
__global__ __launch_bounds__(256)
void gemm_wt_bias(const float* __restrict__ X, const float* __restrict__ W,
                  const float* __restrict__ bias, float* __restrict__ out,
                  float alpha)
{
    constexpr int BM = 128, BN = 128, BK = 16;
    __shared__ float As[BM][BK];
    __shared__ float Bs[BK][BN + 2];

    const int tid = threadIdx.x;
    const int tx = tid & 15, ty = tid >> 4;
    const int row0 = blockIdx.y * BM;
    const int col0 = blockIdx.x * BN;
    const int K = D_MODEL;

    unsigned long long acc[8][4];
#pragma unroll
    for (int i = 0; i < 8; i++)
#pragma unroll
        for (int j = 0; j < 4; j++) acc[i][j] = 0ULL;

    for (int kt = 0; kt < K; kt += BK) {
#pragma unroll
        for (int it = 0; it < 2; it++) {
            int f = tid + it * 256;
            int r = f >> 2, k4 = (f & 3) * 4;
            float4 av = *(const float4*)&X[(size_t)(row0 + r) * K + kt + k4];
            *(float4*)&As[r][k4] = av;
            float4 bv = *(const float4*)&W[(size_t)(col0 + r) * K + kt + k4];
            Bs[k4 + 0][r] = bv.x; Bs[k4 + 1][r] = bv.y;
            Bs[k4 + 2][r] = bv.z; Bs[k4 + 3][r] = bv.w;
        }
        __syncthreads();
#pragma unroll
        for (int k = 0; k < BK; k++) {
            unsigned long long a2[8], b2[4];
#pragma unroll
            for (int i = 0; i < 8; i++) { float a = As[ty * 8 + i][k]; a2[i] = pk2(a, a); }
#pragma unroll
            for (int j = 0; j < 4; j++)
                b2[j] = *(const unsigned long long*)&Bs[k][tx * 2 + 32 * j];
#pragma unroll
            for (int i = 0; i < 8; i++)
#pragma unroll
                for (int j = 0; j < 4; j++)
                    acc[i][j] = ffma2(a2[i], b2[j], acc[i][j]);
        }
        __syncthreads();
    }

    // epilogue: columns col0 + tx*2 + 32*j (+1)
    float bcol[8];
#pragma unroll
    for (int j = 0; j < 4; j++) {
        bcol[2 * j]     = bias[col0 + tx * 2 + 32 * j];
        bcol[2 * j + 1] = bias[col0 + tx * 2 + 32 * j + 1];
    }
#pragma unroll
    for (int i = 0; i < 8; i++) {
        int m = row0 + ty * 8 + i;
#pragma unroll
        for (int j = 0; j < 4; j++) {
            float c0, c1; upk2(acc[i][j], c0, c1);
            c0 = (c0 + bcol[2 * j]) * alpha;
            c1 = (c1 + bcol[2 * j + 1]) * alpha;
            int n0 = col0 + tx * 2 + 32 * j;
            if (MODE == 0) {
                *(float2*)&out[(size_t)m * D_MODEL + n0] = make_float2(c0, c1);
            } else {
                int b = m >> 11, s = m & (SEQ - 1);
                int h = n0 >> 6, d0 = n0 & 63;
                *(float2*)&out[(((size_t)(b * NHEAD + h)) * SEQ + s) * DK + d0] =
                    make_float2(c0, c1);
            }
        }
    }
}

// ---------------- Flash attention (fp32, streaming softmax) ----------------
// APAD=66 (stride ≡ 2 mod 32).
// Phase 1: K loads at k = tx+16j -> conflict-free.
// Phase 3: k-packed. V stored TRANSPOSED (Vt[d][k]); per k-pair one LDS64
//   from Ps (broadcast) + one from Vt (stride-even, conflict-free) feed
//   ffma2 directly -> no splat MOVs. Accumulator lanes = (even-k, odd-k)
//   partials, folded by one horizontal add at the epilogue.
#define BQ   128
#define BKV  64
#define APAD 66

__global__ __launch_bounds__(256)
void flash_attn(const float* __restrict__ Qp, const float* __restrict__ Kp,
                const float* __restrict__ Vp, float* __restrict__ Xo)
{
    extern __shared__ float sm[];
    float (*Qs)[APAD] = (float(*)[APAD])sm;                          // 128 x 66 (q rows)
    float (*Ks)[APAD] = (float(*)[APAD])(sm + BQ * APAD);            // 64 x 66  (k rows)
    float (*Vt)[APAD] = (float(*)[APAD])(sm + (BQ + BKV) * APAD);    // 64 x 66  (d rows!)
    float (*Ps)[APAD] = (float(*)[APAD])(sm + (BQ + 2 * BKV) * APAD);// 128 x 66 (q rows)

    const int tid = threadIdx.x;
    const int tx = tid & 15, ty = tid >> 4;
    const int bh = blockIdx.y;
    const int q0 = blockIdx.x * BQ;

    const float* Qb = Qp + (size_t)bh * SEQ * DK;
    const float* Kb = Kp + (size_t)bh * SEQ * DK;
    const float* Vb = Vp + (size_t)bh * SEQ * DK;

    // Q tile: 128 rows x 64 floats = 4096 float2, 256 threads -> 16 iters
#pragma unroll
    for (int it = 0; it < 16; it++) {
        int f = tid + it * 256;
        int r = f >> 5, c2 = (f & 31) * 2;
        *(float2*)&Qs[r][c2] = *(const float2*)&Qb[(size_t)(q0 + r) * DK + c2];
    }

    float mrow[8], lrow[8];
    unsigned long long ok[8][4];   // [row][m]; d = tx + 16*m; lanes=(even-k,odd-k)
#pragma unroll
    for (int i = 0; i < 8; i++) {
        mrow[i] = -3.0e38f; lrow[i] = 0.f;
#pragma unroll
        for (int m = 0; m < 4; m++) ok[i][m] = 0ULL;
    }

    for (int kv0 = 0; kv0 < SEQ; kv0 += BKV) {
        __syncthreads();   // prior tile's phase-3 must finish before overwrite
#pragma unroll
        for (int it = 0; it < 8; it++) {
            int f = tid + it * 256;
            int r = f >> 5, c2 = (f & 31) * 2;
            *(float2*)&Ks[r][c2] = *(const float2*)&Kb[(size_t)(kv0 + r) * DK + c2];
            float2 vv = *(const float2*)&Vb[(size_t)(kv0 + r) * DK + c2];
            Vt[c2][r]     = vv.x;          // transposed store: Vt[d][k]
            Vt[c2 + 1][r] = vv.y;
        }
        __syncthreads();

        // phase 1: S = Q K^T  (thread: 8 q-rows x 4 k-cols at k = tx+16j)
        unsigned long long sa[8][4];
#pragma unroll
        for (int i = 0; i < 8; i++)
#pragma unroll
            for (int j = 0; j < 4; j++) sa[i][j] = 0ULL;

#pragma unroll 8
        for (int d2 = 0; d2 < 32; d2++) {
            unsigned long long q2[8], k2[4];
#pragma unroll
            for (int i = 0; i < 8; i++)
                q2[i] = *(const unsigned long long*)&Qs[ty * 8 + i][2 * d2];
#pragma unroll
            for (int j = 0; j < 4; j++)
                k2[j] = *(const unsigned long long*)&Ks[tx + 16 * j][2 * d2];
#pragma unroll
            for (int i = 0; i < 8; i++)
#pragma unroll
                for (int j = 0; j < 4; j++)
                    sa[i][j] = ffma2(q2[i], k2[j], sa[i][j]);
        }

        float s[8][4];
#pragma unroll
        for (int i = 0; i < 8; i++)
#pragma unroll
            for (int j = 0; j < 4; j++) {
                float x0, x1; upk2(sa[i][j], x0, x1);
                s[i][j] = x0 + x1;          // scale already folded into Q
            }

        // phase 2: online softmax (16 tx lanes of a row group hold all 64 k)
#pragma unroll
        for (int i = 0; i < 8; i++) {
            float mt = s[i][0];
#pragma unroll
            for (int j = 1; j < 4; j++) mt = fmaxf(mt, s[i][j]);
#pragma unroll
            for (int off = 1; off < 16; off <<= 1)
                mt = fmaxf(mt, __shfl_xor_sync(0xffffffffu, mt, off));
            float mnew = fmaxf(mrow[i], mt);
            float scale = __expf(mrow[i] - mnew);
            float p[4], rs = 0.f;
#pragma unroll
            for (int j = 0; j < 4; j++) { p[j] = __expf(s[i][j] - mnew); rs += p[j]; }
#pragma unroll
            for (int off = 1; off < 16; off <<= 1)
                rs += __shfl_xor_sync(0xffffffffu, rs, off);
            lrow[i] = lrow[i] * scale + rs;
            mrow[i] = mnew;
            unsigned long long sc2 = pk2(scale, scale);
#pragma unroll
            for (int m = 0; m < 4; m++) ok[i][m] = fmul2(ok[i][m], sc2);
            Ps[ty * 8 + i][tx + 16 * 0] = p[0];
            Ps[ty * 8 + i][tx + 16 * 1] = p[1];
            Ps[ty * 8 + i][tx + 16 * 2] = p[2];
            Ps[ty * 8 + i][tx + 16 * 3] = p[3];
        }
        __syncthreads();

        // phase 3: O += P V, packed over (k, k+1). No splats.
#pragma unroll 4
        for (int c = 0; c < BKV / 2; c++) {
            unsigned long long vv[4];
#pragma unroll
            for (int m = 0; m < 4; m++)
                vv[m] = *(const unsigned long long*)&Vt[tx + 16 * m][2 * c];
#pragma unroll
            for (int i = 0; i < 8; i++) {
                unsigned long long p2 =
                    *(const unsigned long long*)&Ps[ty * 8 + i][2 * c];
#pragma unroll
                for (int m = 0; m < 4; m++)
                    ok[i][m] = ffma2(p2, vv[m], ok[i][m]);
            }
        }
    }

    // epilogue: fold (even,odd) lanes, O /= l, write (B,S,D) layout
    const int b = bh >> 4, h = bh & 15;
#pragma unroll
    for (int i = 0; i < 8; i++) {
        float inv = 1.0f / lrow[i];
        size_t srow = (size_t)(q0 + ty * 8 + i);
        size_t base = ((size_t)b * SEQ + srow) * D_MODEL + h * DK;
#pragma unroll
        for (int m = 0; m < 4; m++) {
            float e, o; upk2(ok[i][m], e, o);
            Xo[base + tx + 16 * m] = (e + o) * inv;
        }
    }
}

// ---------------- launch ----------------
extern "C" void kernel_launch(void* const* d_in, const int* in_sizes, int n_in,
                              void* d_out, int out_size)
{
    const float* q  = (const float*)d_in[0];
    const float* k  = (const float*)d_in[1];
    const float* v  = (const float*)d_in[2];
    const float* Wq = (const float*)d_in[3];
    const float* bq = (const float*)d_in[4];
    const float* Wk = (const float*)d_in[5];
    const float* bk = (const float*)d_in[6];
    const float* Wv = (const float*)d_in[7];
    const float* bv = (const float*)d_in[8];
    const float* Wo = (const float*)d_in[9];
    const float* bo = (const float*)d_in[10];
    float* out = (float*)d_out;

    float *gQ, *gK, *gV, *gX;
    cudaGetSymbolAddress((void**)&gQ, g_Q);
    cudaGetSymbolAddress((void**)&gK, g_K);
    cudaGetSymbolAddress((void**)&gV, g_V);
    cudaGetSymbolAddress((void**)&gX, g_X);

    dim3 gg(D_MODEL / 128, MTOT / 128);   // (8, 64)

    // projections; 1/sqrt(dk)=0.125 folded into Q
    gemm_wt_bias<1><<<gg, 256>>>(q, Wq, bq, gQ, 0.125f);
    gemm_wt_bias<1><<<gg, 256>>>(k, Wk, bk, gK, 1.0f);
    gemm_wt_bias<1><<<gg, 256>>>(v, Wv, bv, gV, 1.0f);

    // flash attention
    int smem = (BQ + 2 * BKV + BQ) * APAD * (int)sizeof(float);  // 101376 B
    cudaFuncSetAttribute(flash_attn, cudaFuncAttributeMaxDynamicSharedMemorySize, smem);
    flash_attn<<<dim3(SEQ / BQ, BATCH * NHEAD), 256, smem>>>(gQ, gK, gV, gX);

    // output projection
    gemm_wt_bias<0><<<gg, 256>>>(gX, Wo, bo, out, 1.0f);
}